// round 1
// baseline (speedup 1.0000x reference)
#include <cuda_runtime.h>

// Laplacian pyramid, 5 levels, input (16,3,1024,1024) fp32, edge-clamp padding.
// Output = concat(lpyr0[16,3,1024,1024], lpyr1[...,512,512], lpyr2[...,256,256],
//                 lpyr3[...,128,128], g4[...,64,64])

#define NIMG 48  // 16 * 3

// Scratch for intermediate gaussian levels (allocation-free per harness rules).
__device__ float g_g1[NIMG * 512 * 512];
__device__ float g_g2[NIMG * 256 * 256];
__device__ float g_g3[NIMG * 128 * 128];

// ---------------------------------------------------------------------------
// pyr_reduce: 5x5 binomial, stride 2, edge clamp. One thread per output pixel.
// ---------------------------------------------------------------------------
template <int H, int W>
__global__ void reduce_kernel(const float* __restrict__ in, float* __restrict__ out) {
    constexpr int Ho = H / 2, Wo = W / 2;
    long long idx = (long long)blockIdx.x * blockDim.x + threadIdx.x;
    const long long total = (long long)NIMG * Ho * Wo;
    if (idx >= total) return;

    int x = (int)(idx % Wo);
    int y = (int)((idx / Wo) % Ho);
    long long img = idx / ((long long)Wo * Ho);

    const float* p = in + img * (long long)H * W;
    const float h[5] = {0.0625f, 0.25f, 0.375f, 0.25f, 0.0625f};

    float acc = 0.0f;
#pragma unroll
    for (int a = 0; a < 5; a++) {
        int yy = 2 * y + a - 2;
        yy = yy < 0 ? 0 : (yy >= H ? H - 1 : yy);
        const float* row = p + (long long)yy * W;
        float rs = 0.0f;
#pragma unroll
        for (int b = 0; b < 5; b++) {
            int xx = 2 * x + b - 2;
            xx = xx < 0 ? 0 : (xx >= W ? W - 1 : xx);
            rs = fmaf(h[b], row[xx], rs);
        }
        acc = fmaf(h[a], rs, acc);
    }
    out[idx] = acc;
}

// ---------------------------------------------------------------------------
// Laplacian: lap = fine - expand(coarse). One thread per COARSE pixel, writing
// the corresponding 2x2 fine block. Shares the 3x3 coarse neighborhood across
// all four polyphase outputs; float2 loads/stores on the fine grid.
//
// Polyphase weights (4*h[i]*h[j] factored as (2h)x(2h)):
//   even taps: {0.125, 0.75, 0.125} over rows/cols {i-1, i, i+1} (clamped)
//   odd  taps: {0.5, 0.5}          over rows/cols {i, i+1}      (clamped)
// ---------------------------------------------------------------------------
template <int Hc, int Wc>
__global__ void laplacian_kernel(const float* __restrict__ fine,
                                 const float* __restrict__ coarse,
                                 float* __restrict__ out) {
    constexpr int W = 2 * Wc;
    long long idx = (long long)blockIdx.x * blockDim.x + threadIdx.x;
    const long long total = (long long)NIMG * Hc * Wc;
    if (idx >= total) return;

    int j = (int)(idx % Wc);
    int i = (int)((idx / Wc) % Hc);
    long long img = idx / ((long long)Wc * Hc);

    const float* cp = coarse + img * (long long)Hc * Wc;
    int im1 = i > 0 ? i - 1 : 0;
    int ip1 = i < Hc - 1 ? i + 1 : Hc - 1;
    int jm1 = j > 0 ? j - 1 : 0;
    int jp1 = j < Wc - 1 ? j + 1 : Wc - 1;

    const float* r0 = cp + (long long)im1 * Wc;
    const float* r1 = cp + (long long)i * Wc;
    const float* r2 = cp + (long long)ip1 * Wc;

    float c00 = r0[jm1], c01 = r0[j], c02 = r0[jp1];
    float c10 = r1[jm1], c11 = r1[j], c12 = r1[jp1];
    float c20 = r2[jm1], c21 = r2[j], c22 = r2[jp1];

    // column-combined per row
    float rowE0 = fmaf(0.125f, c00, fmaf(0.75f, c01, 0.125f * c02));
    float rowE1 = fmaf(0.125f, c10, fmaf(0.75f, c11, 0.125f * c12));
    float rowE2 = fmaf(0.125f, c20, fmaf(0.75f, c21, 0.125f * c22));
    float rowO0 = 0.5f * (c01 + c02);
    float rowO1 = 0.5f * (c11 + c12);
    float rowO2 = 0.5f * (c21 + c22);

    float o00 = fmaf(0.125f, rowE0, fmaf(0.75f, rowE1, 0.125f * rowE2));
    float o01 = fmaf(0.125f, rowO0, fmaf(0.75f, rowO1, 0.125f * rowO2));
    float o10 = 0.5f * (rowE1 + rowE2);
    float o11 = 0.5f * (rowO1 + rowO2);

    const float* fp = fine + img * (long long)W * (2 * Hc);
    float* op = out + img * (long long)W * (2 * Hc);
    long long top = (long long)(2 * i) * W + 2 * j;
    long long bot = top + W;

    float2 ftop = *(const float2*)(fp + top);
    float2 fbot = *(const float2*)(fp + bot);

    float2 otop = make_float2(ftop.x - o00, ftop.y - o01);
    float2 obot = make_float2(fbot.x - o10, fbot.y - o11);
    *(float2*)(op + top) = otop;
    *(float2*)(op + bot) = obot;
}

// ---------------------------------------------------------------------------
// Launch
// ---------------------------------------------------------------------------
extern "C" void kernel_launch(void* const* d_in, const int* in_sizes, int n_in,
                              void* d_out, int out_size) {
    const float* im = (const float*)d_in[0];
    float* out = (float*)d_out;

    float* g1;
    float* g2;
    float* g3;
    cudaGetSymbolAddress((void**)&g1, g_g1);
    cudaGetSymbolAddress((void**)&g2, g_g2);
    cudaGetSymbolAddress((void**)&g3, g_g3);

    // output section offsets (elements)
    const long long off0 = 0;
    const long long off1 = off0 + (long long)NIMG * 1024 * 1024;
    const long long off2 = off1 + (long long)NIMG * 512 * 512;
    const long long off3 = off2 + (long long)NIMG * 256 * 256;
    const long long off4 = off3 + (long long)NIMG * 128 * 128;

    const int T = 256;
    auto blocks = [](long long n, int t) { return (unsigned)((n + t - 1) / t); };

    // Gaussian pyramid
    {
        long long n = (long long)NIMG * 512 * 512;
        reduce_kernel<1024, 1024><<<blocks(n, T), T>>>(im, g1);
    }
    {
        long long n = (long long)NIMG * 256 * 256;
        reduce_kernel<512, 512><<<blocks(n, T), T>>>(g1, g2);
    }
    {
        long long n = (long long)NIMG * 128 * 128;
        reduce_kernel<256, 256><<<blocks(n, T), T>>>(g2, g3);
    }
    {
        long long n = (long long)NIMG * 64 * 64;
        reduce_kernel<128, 128><<<blocks(n, T), T>>>(g3, out + off4);  // g4 = lpyr[4]
    }

    // Laplacian levels: lap_l = g_l - expand(g_{l+1})
    {
        long long n = (long long)NIMG * 512 * 512;  // coarse pixels of g1
        laplacian_kernel<512, 512><<<blocks(n, T), T>>>(im, g1, out + off0);
    }
    {
        long long n = (long long)NIMG * 256 * 256;
        laplacian_kernel<256, 256><<<blocks(n, T), T>>>(g1, g2, out + off1);
    }
    {
        long long n = (long long)NIMG * 128 * 128;
        laplacian_kernel<128, 128><<<blocks(n, T), T>>>(g2, g3, out + off2);
    }
    {
        long long n = (long long)NIMG * 64 * 64;
        laplacian_kernel<64, 64><<<blocks(n, T), T>>>(g3, out + off4, out + off3);
    }
}